// round 17
// baseline (speedup 1.0000x reference)
#include <cuda_runtime.h>
#include <cuda_fp16.h>
#include <cstdint>

#define CC 256
#define HWC 3136
#define MM 100352
#define NTH 256
#define STRA 40                 /* halfs per smem row (80B, conflict-free ldmatrix) */
/* GEMM1 (64-row m-tile): AH 5120 | AM 5120 | BH 10240 | BM 10240 = 30720/stage */
#define G1_AM 5120
#define G1_BH 10240
#define G1_BM 20480
#define G1_STG 30720
#define SO1 1024
#define SMEM1 (SO1 + 2*G1_STG)        /* 62464 -> 2 CTAs/SM */
/* GEMM2 (32-row m-tile): ps 1KB | A 2560 + B 20480 = 23040/stage -> 3 CTAs/SM */
#define G2_B   2560
#define G2_STG 23040
#define SO2    1024
#define SMEM2  (SO2 + 2*G2_STG)       /* 47104 */
#define INV2048 (1.0f/2048.0f)
#define INV1024 (1.0f/1024.0f)

// -------------------- device scratch --------------------
__device__ __align__(16) float  g_buf[(size_t)CC*MM];
__device__ __align__(16) unsigned char n_buf[(size_t)CC*MM];       // u8 quant levels
__device__ __align__(16) __half ut_hi_d[CC*CC], ut_mid_d[CC*CC];   // GEMM1 B [j][c]
__device__ __align__(16) __half w_hi_d[CC*CC];                     // GEMM2 B [c][j] = fp16(u*iv*1024)
__device__ float    chsum_d[CC];
__device__ unsigned gmax_d[CC], gmin_d[CC];
__device__ float    mn_d[CC], s_d[CC], dmin_d[CC], scale_d[CC], inv_d[CC], cvv_d[CC];
__device__ float    qsum_d[CC], bias_d[CC], same_d[CC];

// -------------------- helpers --------------------
__device__ __forceinline__ void cp16(uint32_t sdst, const void* g) {
    asm volatile("cp.async.ca.shared.global [%0], [%1], 16;" :: "r"(sdst), "l"(g) : "memory");
}
__device__ __forceinline__ void cp_commit() { asm volatile("cp.async.commit_group;" ::: "memory"); }
__device__ __forceinline__ void cp_wait0()  { asm volatile("cp.async.wait_group 0;" ::: "memory"); }

__device__ __forceinline__ void ldsm4(unsigned* r, uint32_t addr) {
    asm volatile("ldmatrix.sync.aligned.m8n8.x4.shared.b16 {%0,%1,%2,%3}, [%4];"
        : "=r"(r[0]), "=r"(r[1]), "=r"(r[2]), "=r"(r[3]) : "r"(addr));
}
__device__ __forceinline__ void mma16816(float* d, const unsigned* a, const unsigned* b) {
    asm volatile("mma.sync.aligned.m16n8k16.row.col.f32.f16.f16.f32 "
        "{%0,%1,%2,%3}, {%4,%5,%6,%7}, {%8,%9}, {%0,%1,%2,%3};"
        : "+f"(d[0]), "+f"(d[1]), "+f"(d[2]), "+f"(d[3])
        : "r"(a[0]), "r"(a[1]), "r"(a[2]), "r"(a[3]), "r"(b[0]), "r"(b[1]));
}
__device__ __forceinline__ unsigned encf(float f) {
    unsigned u = __float_as_uint(f);
    return (u & 0x80000000u) ? ~u : (u | 0x80000000u);
}
__device__ __forceinline__ float decf(unsigned u) {
    unsigned b = (u & 0x80000000u) ? (u & 0x7FFFFFFFu) : ~u;
    return __uint_as_float(b);
}
__device__ __forceinline__ float qlevel(float g, float sc, float negC, float lo, float hi) {
    return rintf(fminf(fmaxf(fmaf(g, sc, negC), lo), hi));
}

// -------------------- prep --------------------
__global__ void prep_k(const float* __restrict__ u) {
    int t = threadIdx.x, b = blockIdx.x;
    if (b < CC) {
        float val = u[(size_t)b*CC + t];          // u[c=b][j=t]
        __half h = __float2half_rn(val);
        __half e = __float2half_rn((val - __half2float(h)) * 2048.0f);
        ut_hi_d[t*CC + b] = h;  ut_mid_d[t*CC + b] = e;   // [j][c] for GEMM1 B
    } else {
        chsum_d[t] = 0.0f; qsum_d[t] = 0.0f;
        gmax_d[t] = 0u; gmin_d[t] = 0xFFFFFFFFu;
    }
}

// -------------------- GEMM1: g = u^T relu(x), 3-term split, 64-row tiles, 2 CTA/SM ----
__global__ void __launch_bounds__(NTH, 2)
gemm1_k(const float* __restrict__ X)
{
    extern __shared__ char smem[];
    const uint32_t sb = (uint32_t)__cvta_generic_to_shared(smem);
    const int tid = threadIdx.x;
    const int lane = tid & 31, w = tid >> 5;
    const int m0 = blockIdx.y * 64;
    const int by = blockIdx.x;                  // n-half

    const int mg = tid & 15;                    // m-group of 4 rows
    const int cp = tid >> 4;                    // c-pair 0..15
    const int mrow = m0 + mg*4;
    int nimg0 = mrow / HWC;
    size_t abase = (size_t)nimg0*(CC*HWC) + (size_t)(mrow - nimg0*HWC);

    float v[2][4];

    auto loadA = [&](int kc) {
        #pragma unroll
        for (int cc = 0; cc < 2; cc++) {
            int c = kc*32 + cp*2 + cc;
            float4 q = *(const float4*)(X + abase + (size_t)c*HWC);
            v[cc][0]=q.x; v[cc][1]=q.y; v[cc][2]=q.z; v[cc][3]=q.w;
        }
    };
    auto procA = [&](int kc, int st) {
        char* base = smem + SO1 + st*G1_STG;
        #pragma unroll
        for (int cc = 0; cc < 2; cc++) {
            int c = kc*32 + cp*2 + cc;
            float s = 0.f;
            #pragma unroll
            for (int i = 0; i < 4; i++) { v[cc][i] = fmaxf(v[cc][i], 0.f); s += v[cc][i]; }
            s += __shfl_xor_sync(~0u, s, 1); s += __shfl_xor_sync(~0u, s, 2);
            s += __shfl_xor_sync(~0u, s, 4); s += __shfl_xor_sync(~0u, s, 8);
            if (by == 0 && (lane & 15) == 0) atomicAdd(&chsum_d[c], s);
        }
        #pragma unroll
        for (int i = 0; i < 4; i++) {
            __half h0 = __float2half_rn(v[0][i]);
            __half h1 = __float2half_rn(v[1][i]);
            __half e0 = __float2half_rn((v[0][i] - __half2float(h0)) * 2048.0f);
            __half e1 = __float2half_rn((v[1][i] - __half2float(h1)) * 2048.0f);
            uint32_t off = (uint32_t)(((mg*4 + i)*STRA + cp*2) * 2);
            *(__half2*)(base + off)        = __halves2half2(h0, h1);
            *(__half2*)(base + G1_AM + off) = __halves2half2(e0, e1);
        }
    };
    auto prodB = [&](int kc, int st) {
        #pragma unroll
        for (int i = 0; i < 4; i++) {
            int ui = tid + i*NTH;                 // 0..1023
            int ish = (ui < 512);
            int r = (ui & 511) >> 2;              // row 0..127
            int q = ui & 3;
            uint32_t dst = sb + SO1 + st*G1_STG + (ish ? G1_BH : G1_BM)
                         + (uint32_t)(r*80 + q*16);
            const __half* s = (ish ? ut_hi_d : ut_mid_d) + (size_t)(by*128 + r)*CC + kc*32 + q*8;
            cp16(dst, s);
        }
    };

    float acch[2][4][4] = {};
    float accm[2][4][4] = {};
    const int wm = (w & 1) * 32;
    const int wn = (w >> 1) * 32;

    loadA(0);
    procA(0, 0);
    prodB(0, 0); cp_commit();
    loadA(1);

    const int arow = (lane & 15);
    const int asel = (lane >> 4) << 3;
    const int brow = (lane & 7) + ((lane >> 4) << 3);
    const int bsel = ((lane >> 3) & 1) << 3;

    for (int kc = 0; kc < 8; kc++) {
        const int st = kc & 1;
        cp_wait0();
        __syncthreads();

        if (kc < 7) { procA(kc + 1, st ^ 1); prodB(kc + 1, st ^ 1); cp_commit(); }
        if (kc < 6) loadA(kc + 2);

        const uint32_t ahb = sb + SO1 + st*G1_STG;
        const uint32_t bhb = ahb + G1_BH;
        #pragma unroll
        for (int ks = 0; ks < 2; ks++) {
            const int kb = ks*16;
            unsigned ah[2][4], am[2][4];
            #pragma unroll
            for (int mt = 0; mt < 2; mt++) {
                uint32_t ra = ahb + (uint32_t)(((wm + mt*16 + arow)*STRA + kb + asel) * 2);
                ldsm4(ah[mt], ra);
                ldsm4(am[mt], ra + G1_AM);
            }
            #pragma unroll
            for (int ng = 0; ng < 2; ng++) {
                uint32_t rb = bhb + (uint32_t)(((wn + ng*16 + brow)*STRA + kb + bsel) * 2);
                unsigned bh[4], bm[4];
                ldsm4(bh, rb);
                ldsm4(bm, rb + (G1_BM - G1_BH));
                #pragma unroll
                for (int mt = 0; mt < 2; mt++) {
                    mma16816(acch[mt][ng*2],     ah[mt], bh);
                    mma16816(acch[mt][ng*2 + 1], ah[mt], bh + 2);
                    mma16816(accm[mt][ng*2],     ah[mt], bm);
                    mma16816(accm[mt][ng*2 + 1], ah[mt], bm + 2);
                    mma16816(accm[mt][ng*2],     am[mt], bh);
                    mma16816(accm[mt][ng*2 + 1], am[mt], bh + 2);
                }
            }
        }
    }
    __syncthreads();   // stage free -> scr

    float* scr = (float*)(smem + SO1) + w * (32*36);
    #pragma unroll
    for (int mt = 0; mt < 2; mt++)
        #pragma unroll
        for (int nt = 0; nt < 4; nt++)
            #pragma unroll
            for (int i = 0; i < 4; i++) {
                int nl = nt*8 + (lane & 3)*2 + (i & 1);
                int ml = mt*16 + (lane >> 2) + ((i >> 1) << 3);
                scr[nl*36 + ml] = acch[mt][nt][i] + accm[mt][nt][i] * INV2048;
            }
    __syncwarp();
    #pragma unroll 4
    for (int r = 0; r < 32; r++) {
        int j = by*128 + wn + r;
        float val = scr[r*36 + lane];
        float mx = val, mn = val;
        #pragma unroll
        for (int d = 1; d < 32; d <<= 1) {
            mx = fmaxf(mx, __shfl_xor_sync(~0u, mx, d));
            mn = fminf(mn, __shfl_xor_sync(~0u, mn, d));
        }
        g_buf[(size_t)j*MM + m0 + wm + lane] = val;
        if (lane == 0) {
            atomicMax(&gmax_d[j], encf(mx));
            atomicMin(&gmin_d[j], encf(mn));
        }
    }
}

// -------------------- GEMM2: 32-row m-tile, full N, 3 CTAs/SM, u8 consumer --------
__global__ void __launch_bounds__(NTH, 3)
gemm2_k(float* __restrict__ OUT)
{
    extern __shared__ char smem[];
    const uint32_t sb = (uint32_t)__cvta_generic_to_shared(smem);
    const int tid = threadIdx.x;
    const int lane = tid & 31, w = tid >> 5;
    const int m0 = blockIdx.x * 32;

    float* ps = (float*)smem;
    ps[tid] = bias_d[tid];
    __syncthreads();

    const int mg = tid & 7;        // m-quad 0..7 (8 x 4 = 32 rows)
    const int cp = tid >> 3;       // c 0..31
    const int mrow = m0 + mg*4;

    unsigned va;
    auto loadA = [&](int kc) {
        int c = kc*32 + cp;
        va = *(const unsigned*)(n_buf + (size_t)c*MM + mrow);
    };
    auto procA = [&](int kc, int st) {
        char* base = smem + SO2 + st*G2_STG;
        #pragma unroll
        for (int i = 0; i < 4; i++) {
            unsigned b0 = (va >> (8*i)) & 0xFFu;
            uint32_t off = (uint32_t)(((mg*4 + i)*STRA + cp) * 2);
            *(__half*)(base + off) = __ushort2half_rn((unsigned short)b0);
        }
    };
    auto prodB = [&](int kc, int st) {
        #pragma unroll
        for (int i = 0; i < 4; i++) {
            int ui = tid + i*NTH;                 // 0..1023
            int r = ui >> 2;                      // row 0..255
            int q = ui & 3;
            uint32_t dst = sb + SO2 + st*G2_STG + G2_B + (uint32_t)(r*80 + q*16);
            cp16(dst, w_hi_d + (size_t)r*CC + kc*32 + q*8);
        }
    };

    float acc[8][4] = {};          // m16 x n64 per warp
    const int wm = (w & 1) * 16;
    const int wn = (w >> 1) * 64;

    loadA(0);
    procA(0, 0);
    prodB(0, 0); cp_commit();
    loadA(1);

    const int arow = (lane & 15);
    const int asel = (lane >> 4) << 3;
    const int brow = (lane & 7) + ((lane >> 4) << 3);
    const int bsel = ((lane >> 3) & 1) << 3;

    for (int kc = 0; kc < 8; kc++) {
        const int st = kc & 1;
        cp_wait0();
        __syncthreads();

        if (kc < 7) { procA(kc + 1, st ^ 1); prodB(kc + 1, st ^ 1); cp_commit(); }
        if (kc < 6) loadA(kc + 2);

        const uint32_t ahb = sb + SO2 + st*G2_STG;
        const uint32_t bhb = ahb + G2_B;
        #pragma unroll
        for (int ks = 0; ks < 2; ks++) {
            const int kb = ks*16;
            unsigned ah[4];
            uint32_t ra = ahb + (uint32_t)(((wm + arow)*STRA + kb + asel) * 2);
            ldsm4(ah, ra);
            #pragma unroll
            for (int ng = 0; ng < 4; ng++) {
                uint32_t rb = bhb + (uint32_t)(((wn + ng*16 + brow)*STRA + kb + bsel) * 2);
                unsigned bh[4];
                ldsm4(bh, rb);
                mma16816(acc[ng*2],     ah, bh);
                mma16816(acc[ng*2 + 1], ah, bh + 2);
            }
        }
    }
    __syncthreads();   // stage free -> scr

    float* scr = (float*)(smem + SO2) + w * (64*20);
    #pragma unroll
    for (int nt = 0; nt < 8; nt++)
        #pragma unroll
        for (int i = 0; i < 4; i++) {
            int nl = nt*8 + (lane & 3)*2 + (i & 1);
            int ml = (lane >> 2) + ((i >> 1) << 3);
            scr[nl*20 + ml] = acc[nt][i] * INV1024;
        }
    __syncwarp();

    // writes: lanes 0-15 -> c = wn+2r, lanes 16-31 -> c = wn+2r+1
    int mstart = m0 + wm;
    int nimg = mstart / HWC;
    size_t base = (size_t)nimg*(CC*HWC) + (size_t)(mstart - nimg*HWC);
    int half = lane >> 4, ml = lane & 15;
    #pragma unroll 4
    for (int r = 0; r < 32; r++) {
        int c = wn + r*2 + half;
        OUT[base + (size_t)c*HWC + ml] = scr[(r*2 + half)*20 + ml] + ps[c];
    }
}

// -------------------- mid: quant params + fused wsplit --------------------
__global__ void mid_k(const float* __restrict__ u, const float* __restrict__ cv,
                      const int* __restrict__ abw) {
    __shared__ float mns[CC];
    __shared__ float ivs[CC];
    int t = threadIdx.x;
    float mn = chsum_d[t] * (1.0f / (float)MM);
    mn_d[t] = mn; mns[t] = mn;
    __syncthreads();
    float s = 0.0f;
    #pragma unroll 8
    for (int c = 0; c < CC; c++) s += u[(size_t)c*CC + t] * mns[c];
    s_d[t] = s;
    float c = cv[t]; cvv_d[t] = c;
    int ab = abw ? *abw : 8;
    float dmax = fminf(fmaxf(decf(gmax_d[t]) - s, -c), c);
    float dmin = fminf(fmaxf(decf(gmin_d[t]) - s, -c), c);
    int same = (dmax == dmin) || (ab >= 17);
    float rng = same ? 1.0f : (dmax - dmin);
    float levels = (float)((1 << (same ? 8 : ab)) - 1);
    same_d[t]  = same ? 1.0f : 0.0f;
    dmin_d[t]  = dmin;
    scale_d[t] = levels / rng;
    float iv = rng / levels;
    inv_d[t]   = iv;
    ivs[t] = iv * 1024.0f;
    __syncthreads();
    for (int idx = t; idx < CC*CC; idx += CC) {
        int j = idx & 255;
        w_hi_d[idx] = __float2half_rn(u[idx] * ivs[j]);
    }
}

// -------------------- qsum: u8 levels + sum(n), MLP-2, 256 threads --------------------
__global__ void __launch_bounds__(256, 2) qsum_k() {
    __shared__ float red[8];
    int j = blockIdx.y;
    float s = s_d[j], dm = dmin_d[j], sc = scale_d[j], cv = cvv_d[j];
    float NC = -(s + dm) * sc;
    float LO = (-cv - dm) * sc;
    float HI = (cv - dm) * sc;
    size_t eoff = (size_t)blockIdx.x*2048 + threadIdx.x*4;
    const float* gp = g_buf + (size_t)j*MM;
    unsigned char* np = n_buf + (size_t)j*MM;
    float4 va = *(const float4*)(gp + eoff);
    float4 vb = *(const float4*)(gp + eoff + 1024);
    float n0 = qlevel(va.x, sc, NC, LO, HI), n1 = qlevel(va.y, sc, NC, LO, HI);
    float n2 = qlevel(va.z, sc, NC, LO, HI), n3 = qlevel(va.w, sc, NC, LO, HI);
    float n4 = qlevel(vb.x, sc, NC, LO, HI), n5 = qlevel(vb.y, sc, NC, LO, HI);
    float n6 = qlevel(vb.z, sc, NC, LO, HI), n7 = qlevel(vb.w, sc, NC, LO, HI);
    *(unsigned*)(np + eoff) = (unsigned)(int)n0 | ((unsigned)(int)n1 << 8)
                            | ((unsigned)(int)n2 << 16) | ((unsigned)(int)n3 << 24);
    *(unsigned*)(np + eoff + 1024) = (unsigned)(int)n4 | ((unsigned)(int)n5 << 8)
                            | ((unsigned)(int)n6 << 16) | ((unsigned)(int)n7 << 24);
    float sum = n0+n1+n2+n3+n4+n5+n6+n7;
    #pragma unroll
    for (int d = 1; d < 32; d <<= 1) sum += __shfl_xor_sync(~0u, sum, d);
    int lane = threadIdx.x & 31, wid = threadIdx.x >> 5;
    if (lane == 0) red[wid] = sum;
    __syncthreads();
    if (threadIdx.x < 8) {
        float r = red[threadIdx.x];
        #pragma unroll
        for (int d = 1; d < 8; d <<= 1) r += __shfl_xor_sync(0xffu, r, d);
        if (threadIdx.x == 0) atomicAdd(&qsum_d[j], r);
    }
}

// -------------------- bias2[c] = mn[c] - sum_j u[c][j]*iv[j]*nmean[j] ----------------
__global__ void bias_k(const float* __restrict__ u) {
    __shared__ float dq[CC];
    int t = threadIdx.x;
    dq[t] = -inv_d[t] * qsum_d[t] * (1.0f / (float)MM);
    __syncthreads();
    float b = 0.0f;
    #pragma unroll 8
    for (int j = 0; j < CC; j++) b += u[(size_t)t*CC + j] * dq[j];
    bias_d[t] = mn_d[t] + b;
}

// -------------------- launcher --------------------
extern "C" void kernel_launch(void* const* d_in, const int* in_sizes, int n_in,
                              void* d_out, int out_size) {
    const float* x  = (const float*)d_in[0];
    const float* u  = (const float*)d_in[1];
    const float* cv = (const float*)d_in[2];
    const int*   ab = (n_in > 3) ? (const int*)d_in[3] : nullptr;
    float* out = (float*)d_out;
    (void)in_sizes; (void)out_size;

    cudaFuncSetAttribute(gemm1_k, cudaFuncAttributeMaxDynamicSharedMemorySize, SMEM1);
    cudaFuncSetAttribute(gemm2_k, cudaFuncAttributeMaxDynamicSharedMemorySize, SMEM2);

    prep_k<<<CC + 1, CC>>>(u);
    gemm1_k<<<dim3(2, MM/64), NTH, SMEM1>>>(x);        // 64-row tiles, 2 CTAs/SM
    mid_k<<<1, CC>>>(u, cv, ab);                       // + fused wsplit
    qsum_k<<<dim3(MM/2048, CC), 256>>>();              // levels -> n_buf (u8), MLP-2
    bias_k<<<1, CC>>>(u);
    gemm2_k<<<dim3(MM/32, 1), NTH, SMEM2>>>(out);      // 32-row tiles, 3 CTAs/SM
}